// round 2
// baseline (speedup 1.0000x reference)
#include <cuda_runtime.h>
#include <math.h>

// Problem constants (fixed by the dataset)
#define SD 5
#define OD 32
#define NB 256
#define TT 8192

// ---------------- scratch (device globals; allocation-free) ----------------
// proj layout: [(t*6+k)*NB + b], k=0..4 -> (C^T R^-1 y)_k, k=5 -> y^T R^-1 y
__device__ float  g_proj[TT * 6 * NB];     // 12,582,912 floats = 50.3 MB
// J layout: [t*26 + e], e<25 = P_post (row-major), e=25 = logdet S_t
__device__ float  g_J[TT * 26];
__device__ float  g_U[25];                 // U = C^T R^-1 C
__device__ double g_llpart[128 * NB];      // per (z-chunk, batch) partial ll

// ---------------- phase-1 config ----------------
#define R_LR 8                      // Riccati chunk length (owned steps)
#define R_WR 24                     // Riccati warmup steps
#define R_NBLK 4                    // 4 blocks * 256 threads = 1024 chunks
#define P_TPB 2                     // t's per projection block
#define P_NBLK (TT / P_TPB)         // 4096 projection blocks
#define P_SMEM (P_TPB * NB * 33 * 4)

// ---------------- phase-2 config ----------------
#define Z_L 64                      // z-chunk owned length
#define Z_W 64                      // z warmup
#define Z_NCHUNK (TT / Z_L)         // 128
#define Z_MAXSTEPS (Z_L + Z_W)      // 128
#define Z_FLUSH 16                  // states staging depth
#define BC_NBLK 896                 // covariance-broadcast blocks
#define Z_SMEM (Z_MAXSTEPS * 26 * 4 + NB * 81 * 4)   // 13312 + 82944 = 96256

// output offsets (tuple flattened: states, covs, ll)
#define OUT_STATES 0
#define OUT_COVS   ((size_t)NB * TT * SD)                       // 10,485,760
#define OUT_LL     (OUT_COVS + (size_t)NB * TT * SD * SD)       // 62,914,816

// ============================================================================
// Phase 1: (a) data-independent Riccati recursion -> g_J   [blocks 0..3]
//          (b) observation projection y -> g_proj          [blocks 4..4099]
// ============================================================================
__global__ __launch_bounds__(256) void k_phase1(
    const float* __restrict__ y,
    const float* __restrict__ Ain,
    const float* __restrict__ Cin,
    const float* __restrict__ Qlog,
    const float* __restrict__ Rlog)
{
    extern __shared__ float sy[];   // proj: [P_TPB][NB][33] padded y tile
    const int tid = threadIdx.x;

    if (blockIdx.x < R_NBLK) {
        // -------- Riccati: one chunk per thread, 1024 chunks --------
        const int chunk = blockIdx.x * 256 + tid;

        float a[25];
        #pragma unroll
        for (int i = 0; i < 25; i++) a[i] = Ain[i];

        float q[5];
        #pragma unroll
        for (int k = 0; k < 5; k++) q[k] = expf(Qlog[k]);

        float U[25];
        #pragma unroll
        for (int i = 0; i < 25; i++) U[i] = 0.f;
        float logdetR = 0.f;
        for (int o = 0; o < OD; o++) {
            float rl = Rlog[o];
            logdetR += rl;
            float ri = expf(-rl);
            float cv[5];
            #pragma unroll
            for (int k = 0; k < 5; k++) cv[k] = Cin[o * 5 + k];
            #pragma unroll
            for (int i = 0; i < 5; i++) {
                float f = ri * cv[i];
                #pragma unroll
                for (int j = 0; j < 5; j++) U[i * 5 + j] += f * cv[j];
            }
        }
        if (chunk == 0) {
            #pragma unroll
            for (int i = 0; i < 25; i++) g_U[i] = U[i];
        }

        const int town = chunk * R_LR;
        const int tend = town + R_LR;
        int t0s = town - R_WR; if (t0s < 0) t0s = 0;

        float P[25];
        #pragma unroll
        for (int i = 0; i < 25; i++) P[i] = (i % 6 == 0) ? 1.f : 0.f;

        for (int t = t0s; t < tend; ++t) {
            float Tm[25], Pp[25];
            // Tm = A * P
            #pragma unroll
            for (int i = 0; i < 5; i++)
                #pragma unroll
                for (int j = 0; j < 5; j++) {
                    float s = 0.f;
                    #pragma unroll
                    for (int k = 0; k < 5; k++) s += a[i * 5 + k] * P[k * 5 + j];
                    Tm[i * 5 + j] = s;
                }
            // Pp = Tm * A^T + diag(q)
            #pragma unroll
            for (int i = 0; i < 5; i++)
                #pragma unroll
                for (int j = 0; j < 5; j++) {
                    float s = 0.f;
                    #pragma unroll
                    for (int k = 0; k < 5; k++) s += Tm[i * 5 + k] * a[j * 5 + k];
                    Pp[i * 5 + j] = s;
                }
            #pragma unroll
            for (int i = 0; i < 5; i++) Pp[i * 5 + i] += q[i];

            // M = I + U * Pp  (strongly diagonally dominant -> pivotless GJ)
            float M[25];
            #pragma unroll
            for (int i = 0; i < 5; i++)
                #pragma unroll
                for (int j = 0; j < 5; j++) {
                    float s = (i == j) ? 1.f : 0.f;
                    #pragma unroll
                    for (int k = 0; k < 5; k++) s += U[i * 5 + k] * Pp[k * 5 + j];
                    M[i * 5 + j] = s;
                }
            // Gauss-Jordan inverse + det
            float V[25];
            #pragma unroll
            for (int i = 0; i < 25; i++) V[i] = (i % 6 == 0) ? 1.f : 0.f;
            float det = 1.f;
            #pragma unroll
            for (int k = 0; k < 5; k++) {
                float piv = M[k * 5 + k];
                det *= piv;
                float ip = 1.f / piv;
                #pragma unroll
                for (int j = 0; j < 5; j++) { M[k * 5 + j] *= ip; V[k * 5 + j] *= ip; }
                #pragma unroll
                for (int i2 = 0; i2 < 5; i2++) {
                    if (i2 == k) continue;
                    float f = M[i2 * 5 + k];
                    #pragma unroll
                    for (int j = 0; j < 5; j++) {
                        M[i2 * 5 + j] -= f * M[k * 5 + j];
                        V[i2 * 5 + j] -= f * V[k * 5 + j];
                    }
                }
            }
            // J = Pp * V  -> becomes next P (posterior covariance)
            #pragma unroll
            for (int i = 0; i < 5; i++)
                #pragma unroll
                for (int j = 0; j < 5; j++) {
                    float s = 0.f;
                    #pragma unroll
                    for (int k = 0; k < 5; k++) s += Pp[i * 5 + k] * V[k * 5 + j];
                    P[i * 5 + j] = s;
                }

            if (t >= town) {
                float ld = logdetR + logf(det);
                #pragma unroll
                for (int e = 0; e < 25; e++) g_J[t * 26 + e] = P[e];
                g_J[t * 26 + 25] = ld;
            }
        }
    } else {
        // -------- projection: block = 2 time-steps x all 256 batches --------
        const int v = blockIdx.x - R_NBLK;
        const int tbase = v * P_TPB;

        __shared__ float crv[OD * 5];
        __shared__ float rin[OD];
        if (tid < OD * 5) {
            int o = tid / 5;
            crv[tid] = Cin[tid] * expf(-Rlog[o]);
        } else if (tid < OD * 5 + OD) {
            rin[tid - OD * 5] = expf(-Rlog[tid - OD * 5]);
        }

        // coalesced load of y[b][tbase..tbase+1][0..31] into padded smem
        const int lane = tid & 31;
        const int w = tid >> 5;
        for (int r = w; r < P_TPB * NB; r += 8) {
            int tt = r >> 8;        // r / 256
            int b  = r & 255;
            sy[(tt * NB + b) * 33 + lane] =
                y[((size_t)b * TT + tbase + tt) * OD + lane];
        }
        __syncthreads();

        const int b = tid;
        #pragma unroll
        for (int tt = 0; tt < P_TPB; ++tt) {
            float c0 = 0, c1 = 0, c2 = 0, c3 = 0, c4 = 0, syy = 0;
            const float* row = &sy[(tt * NB + b) * 33];
            #pragma unroll
            for (int o = 0; o < OD; o++) {
                float yv = row[o];
                syy += (yv * rin[o]) * yv;
                c0 += crv[o * 5 + 0] * yv;
                c1 += crv[o * 5 + 1] * yv;
                c2 += crv[o * 5 + 2] * yv;
                c3 += crv[o * 5 + 3] * yv;
                c4 += crv[o * 5 + 4] * yv;
            }
            int t = tbase + tt;
            float* pd = &g_proj[((size_t)t * 6) * NB + b];
            pd[0 * NB] = c0; pd[1 * NB] = c1; pd[2 * NB] = c2;
            pd[3 * NB] = c3; pd[4 * NB] = c4; pd[5 * NB] = syy;
        }
    }
}

// ============================================================================
// Phase 2: (a) z-recursion + states + ll partials   [blocks 0..127]
//          (b) covariance broadcast J -> covs       [blocks 128..1023]
// ============================================================================
__global__ __launch_bounds__(256) void k_phase2(
    const float* __restrict__ Ain, float* __restrict__ out)
{
    extern __shared__ float sm[];
    const int tid = threadIdx.x;

    if (blockIdx.x < Z_NCHUNK) {
        float* sJ   = sm;                       // [nsteps][26]
        float* sbuf = sm + Z_MAXSTEPS * 26;     // [NB][81] states staging

        const int chunk = blockIdx.x;
        const int town = chunk * Z_L;
        int t0 = town - Z_W; if (t0 < 0) t0 = 0;
        const int nsteps = town + Z_L - t0;
        const int warm = town - t0;

        for (int i = tid; i < nsteps * 26; i += 256) sJ[i] = g_J[t0 * 26 + i];
        __syncthreads();

        float a[25], U[25];
        #pragma unroll
        for (int i = 0; i < 25; i++) { a[i] = Ain[i]; U[i] = g_U[i]; }

        float z0 = 0, z1 = 0, z2 = 0, z3 = 0, z4 = 0;
        double ll = 0.0;
        const int b = tid;
        const float* pj = &g_proj[((size_t)t0 * 6) * NB + b];

        for (int s = 0; s < nsteps; ++s) {
            float cc[5], syy;
            #pragma unroll
            for (int k = 0; k < 5; k++) cc[k] = pj[k * NB];
            syy = pj[5 * NB];
            pj += 6 * NB;

            float zp[5];
            #pragma unroll
            for (int i = 0; i < 5; i++)
                zp[i] = a[i * 5 + 0] * z0 + a[i * 5 + 1] * z1 + a[i * 5 + 2] * z2
                      + a[i * 5 + 3] * z3 + a[i * 5 + 4] * z4;
            float g[5];
            #pragma unroll
            for (int i = 0; i < 5; i++) {
                float sa = 0.f;
                #pragma unroll
                for (int j = 0; j < 5; j++) sa += U[i * 5 + j] * zp[j];
                g[i] = sa;
            }
            float w[5];
            #pragma unroll
            for (int i = 0; i < 5; i++) w[i] = cc[i] - g[i];
            const float* Jr = &sJ[s * 26];
            float h[5];
            #pragma unroll
            for (int i = 0; i < 5; i++) {
                float sa = 0.f;
                #pragma unroll
                for (int j = 0; j < 5; j++) sa += Jr[i * 5 + j] * w[j];
                h[i] = sa;
            }
            z0 = zp[0] + h[0]; z1 = zp[1] + h[1]; z2 = zp[2] + h[2];
            z3 = zp[3] + h[3]; z4 = zp[4] + h[4];

            if (s >= warm) {
                float cz = 0, zg = 0, wh = 0;
                #pragma unroll
                for (int i = 0; i < 5; i++) {
                    cz += cc[i] * zp[i]; zg += zp[i] * g[i]; wh += w[i] * h[i];
                }
                float quad = syy - 2.f * cz + zg - wh;
                ll -= 0.5 * ((double)OD * 1.8378770664093453
                             + (double)Jr[25] + (double)quad);

                // stage states, flush coalesced every Z_FLUSH steps
                int sl = (s - warm) & (Z_FLUSH - 1);
                float* sb = &sbuf[b * 81 + sl * 5];
                sb[0] = z0; sb[1] = z1; sb[2] = z2; sb[3] = z3; sb[4] = z4;
                if (sl == Z_FLUSH - 1) {
                    __syncthreads();
                    int tflush0 = town + ((s - warm) & ~(Z_FLUSH - 1));
                    for (int f = tid; f < NB * Z_FLUSH * 5; f += 256) {
                        int bb = f / (Z_FLUSH * 5);
                        int u  = f % (Z_FLUSH * 5);
                        out[OUT_STATES + ((size_t)bb * TT + tflush0) * 5 + u]
                            = sbuf[bb * 81 + u];
                    }
                    __syncthreads();
                }
            }
        }
        g_llpart[chunk * NB + b] = ll;
    } else {
        // covariance broadcast: covs[b][t][:] = J[t][:]
        unsigned idx = (unsigned)(blockIdx.x - Z_NCHUNK) * 256u + tid;
        const unsigned total = (unsigned)NB * TT * 25u;   // 52,428,800
        const unsigned stride = (unsigned)BC_NBLK * 256u;
        for (; idx < total; idx += stride) {
            unsigned e  = idx % 25u;
            unsigned bt = idx / 25u;
            unsigned t  = bt & (TT - 1);
            out[OUT_COVS + idx] = g_J[t * 26u + e];
        }
    }
}

// ============================================================================
// Phase 3: deterministic ll reduction over z-chunks
// ============================================================================
__global__ void k_phase3(float* __restrict__ out)
{
    int b = threadIdx.x;
    double s = 0.0;
    for (int c = 0; c < Z_NCHUNK; c++) s += g_llpart[c * NB + b];
    out[OUT_LL + b] = (float)s;
}

// ============================================================================
extern "C" void kernel_launch(void* const* d_in, const int* in_sizes, int n_in,
                              void* d_out, int out_size)
{
    const float* y  = (const float*)d_in[0];
    const float* A  = (const float*)d_in[1];
    const float* C  = (const float*)d_in[2];
    const float* Ql = (const float*)d_in[3];
    const float* Rl = (const float*)d_in[4];
    float* out = (float*)d_out;

    cudaFuncSetAttribute(k_phase1, cudaFuncAttributeMaxDynamicSharedMemorySize, P_SMEM);
    cudaFuncSetAttribute(k_phase2, cudaFuncAttributeMaxDynamicSharedMemorySize, Z_SMEM);

    k_phase1<<<R_NBLK + P_NBLK, 256, P_SMEM>>>(y, A, C, Ql, Rl);
    k_phase2<<<Z_NCHUNK + BC_NBLK, 256, Z_SMEM>>>(A, out);
    k_phase3<<<1, 256>>>(out);
}

// round 3
// speedup vs baseline: 1.3176x; 1.3176x over previous
#include <cuda_runtime.h>
#include <math.h>

// Problem constants (fixed by the dataset)
#define SD 5
#define OD 32
#define NB 256
#define TT 8192

// ---------------- scratch (device globals; allocation-free) ----------------
// proj layout: [(t*6+k)*NB + b], k=0..4 -> (C^T R^-1 y)_k, k=5 -> y^T R^-1 y
__device__ float  g_proj[TT * 6 * NB];     // 50.3 MB
// J layout: [t*26 + e], e<25 = P_post (row-major), e=25 = logdet S_t
__device__ float  g_J[TT * 26];
__device__ float  g_U[25];                 // U = C^T R^-1 C
__device__ double g_llpart[128 * NB];      // per (z-chunk, batch) partial ll

// ---------------- Riccati config ----------------
#define R_LR 8                      // owned steps per chunk
#define R_WR 24                     // warmup steps
#define R_NBLK 32                   // 32 blocks * 32 threads = 1024 chunks

// ---------------- projection config ----------------
#define P_TPB 8                     // t's per block
#define P_NBLK (TT / P_TPB)         // 1024 blocks

// ---------------- z-recursion / broadcast config ----------------
#define Z_L 64
#define Z_W 64
#define Z_NCHUNK (TT / Z_L)         // 128
#define Z_MAXSTEPS (Z_L + Z_W)      // 128
#define Z_FLUSH 8
#define BC_TILE 32                  // t's per broadcast tile
#define BC_NBLK (TT / BC_TILE)      // 256
// smem: sJ 128*26 floats (13312B) + sbuf 256*41 floats (41984B) = 55296B
#define ZB_SMEM (Z_MAXSTEPS * 26 * 4 + NB * 41 * 4)

// output offsets (tuple flattened: states, covs, ll)
#define OUT_STATES 0
#define OUT_COVS   ((size_t)NB * TT * SD)
#define OUT_LL     (OUT_COVS + (size_t)NB * TT * SD * SD)

// ============================================================================
// Kernel 1: data-independent Riccati recursion -> g_J, g_U
// 1024 chunks spread as 32 blocks x 32 threads (1 warp/SM, latency-bound)
// ============================================================================
__global__ __launch_bounds__(32) void k_ricc(
    const float* __restrict__ Ain,
    const float* __restrict__ Cin,
    const float* __restrict__ Qlog,
    const float* __restrict__ Rlog)
{
    const int chunk = blockIdx.x * 32 + threadIdx.x;

    float a[25];
    #pragma unroll
    for (int i = 0; i < 25; i++) a[i] = Ain[i];
    float q[5];
    #pragma unroll
    for (int k = 0; k < 5; k++) q[k] = expf(Qlog[k]);

    float U[25];
    #pragma unroll
    for (int i = 0; i < 25; i++) U[i] = 0.f;
    float logdetR = 0.f;
    for (int o = 0; o < OD; o++) {
        float rl = Rlog[o];
        logdetR += rl;
        float ri = expf(-rl);
        float cv[5];
        #pragma unroll
        for (int k = 0; k < 5; k++) cv[k] = Cin[o * 5 + k];
        #pragma unroll
        for (int i = 0; i < 5; i++) {
            float f = ri * cv[i];
            #pragma unroll
            for (int j = 0; j < 5; j++) U[i * 5 + j] += f * cv[j];
        }
    }
    if (chunk == 0) {
        #pragma unroll
        for (int i = 0; i < 25; i++) g_U[i] = U[i];
    }

    const int town = chunk * R_LR;
    const int tend = town + R_LR;
    int t0s = town - R_WR; if (t0s < 0) t0s = 0;

    float P[25];
    #pragma unroll
    for (int i = 0; i < 25; i++) P[i] = (i % 6 == 0) ? 1.f : 0.f;

    for (int t = t0s; t < tend; ++t) {
        float Tm[25], Pp[25];
        #pragma unroll
        for (int i = 0; i < 5; i++)
            #pragma unroll
            for (int j = 0; j < 5; j++) {
                float s = 0.f;
                #pragma unroll
                for (int k = 0; k < 5; k++) s += a[i * 5 + k] * P[k * 5 + j];
                Tm[i * 5 + j] = s;
            }
        #pragma unroll
        for (int i = 0; i < 5; i++)
            #pragma unroll
            for (int j = 0; j < 5; j++) {
                float s = 0.f;
                #pragma unroll
                for (int k = 0; k < 5; k++) s += Tm[i * 5 + k] * a[j * 5 + k];
                Pp[i * 5 + j] = s;
            }
        #pragma unroll
        for (int i = 0; i < 5; i++) Pp[i * 5 + i] += q[i];

        // M = I + U*Pp ; invert via pivotless Gauss-Jordan (diag-dominant)
        float M[25], V[25];
        #pragma unroll
        for (int i = 0; i < 5; i++)
            #pragma unroll
            for (int j = 0; j < 5; j++) {
                float s = (i == j) ? 1.f : 0.f;
                #pragma unroll
                for (int k = 0; k < 5; k++) s += U[i * 5 + k] * Pp[k * 5 + j];
                M[i * 5 + j] = s;
            }
        #pragma unroll
        for (int i = 0; i < 25; i++) V[i] = (i % 6 == 0) ? 1.f : 0.f;
        float det = 1.f;
        #pragma unroll
        for (int k = 0; k < 5; k++) {
            float piv = M[k * 5 + k];
            det *= piv;
            float ip = 1.f / piv;
            #pragma unroll
            for (int j = 0; j < 5; j++) { M[k * 5 + j] *= ip; V[k * 5 + j] *= ip; }
            #pragma unroll
            for (int i2 = 0; i2 < 5; i2++) {
                if (i2 == k) continue;
                float f = M[i2 * 5 + k];
                #pragma unroll
                for (int j = 0; j < 5; j++) {
                    M[i2 * 5 + j] -= f * M[k * 5 + j];
                    V[i2 * 5 + j] -= f * V[k * 5 + j];
                }
            }
        }
        // P_post = Pp * V
        #pragma unroll
        for (int i = 0; i < 5; i++)
            #pragma unroll
            for (int j = 0; j < 5; j++) {
                float s = 0.f;
                #pragma unroll
                for (int k = 0; k < 5; k++) s += Pp[i * 5 + k] * V[k * 5 + j];
                P[i * 5 + j] = s;
            }

        if (t >= town) {
            float ld = logdetR + logf(det);
            #pragma unroll
            for (int e = 0; e < 25; e++) g_J[t * 26 + e] = P[e];
            g_J[t * 26 + 25] = ld;
        }
    }
}

// ============================================================================
// Kernel 2: observation projection y -> g_proj
// Thread = one batch row; each thread reads its own full 128B y-row via
// 8x LDG.128 (every byte of every line used), computes 6 dot products.
// ============================================================================
__global__ __launch_bounds__(256) void k_proj(
    const float* __restrict__ y,
    const float* __restrict__ Cin,
    const float* __restrict__ Rlog)
{
    __shared__ float crv[OD * 5];   // (C^T R^-1)[k][o] interleaved [o*5+k]
    __shared__ float rin[OD];
    const int tid = threadIdx.x;
    if (tid < OD * 5) {
        int o = tid / 5;
        crv[tid] = Cin[tid] * expf(-Rlog[o]);
    } else if (tid < OD * 5 + OD) {
        rin[tid - OD * 5] = expf(-Rlog[tid - OD * 5]);
    }
    __syncthreads();

    const int b = tid;
    const int t0 = blockIdx.x * P_TPB;

    #pragma unroll
    for (int tt = 0; tt < P_TPB; ++tt) {
        const int t = t0 + tt;
        const float4* yp = (const float4*)(y + ((size_t)b * TT + t) * OD);
        float v[OD];
        #pragma unroll
        for (int q = 0; q < 8; q++) {
            float4 f = yp[q];
            v[q * 4 + 0] = f.x; v[q * 4 + 1] = f.y;
            v[q * 4 + 2] = f.z; v[q * 4 + 3] = f.w;
        }
        float c0 = 0, c1 = 0, c2 = 0, c3 = 0, c4 = 0, syy = 0;
        #pragma unroll
        for (int o = 0; o < OD; o++) {
            float yv = v[o];
            syy += (yv * rin[o]) * yv;
            c0 += crv[o * 5 + 0] * yv;
            c1 += crv[o * 5 + 1] * yv;
            c2 += crv[o * 5 + 2] * yv;
            c3 += crv[o * 5 + 3] * yv;
            c4 += crv[o * 5 + 4] * yv;
        }
        float* pd = &g_proj[((size_t)t * 6) * NB + b];
        pd[0 * NB] = c0; pd[1 * NB] = c1; pd[2 * NB] = c2;
        pd[3 * NB] = c3; pd[4 * NB] = c4; pd[5 * NB] = syy;
    }
}

// ============================================================================
// Kernel 3: (a) z-recursion + states + ll partials   [blocks 0..127]
//           (b) covariance broadcast J -> covs        [blocks 128..383]
// ============================================================================
__global__ __launch_bounds__(256) void k_zb(
    const float* __restrict__ Ain, float* __restrict__ out)
{
    extern __shared__ float sm[];
    const int tid = threadIdx.x;

    if (blockIdx.x < Z_NCHUNK) {
        float* sJ   = sm;                       // [nsteps][26]
        float* sbuf = sm + Z_MAXSTEPS * 26;     // [NB][41] states staging

        const int chunk = blockIdx.x;
        const int town = chunk * Z_L;
        int t0 = town - Z_W; if (t0 < 0) t0 = 0;
        const int nsteps = town + Z_L - t0;
        const int warm = town - t0;

        for (int i = tid; i < nsteps * 26; i += 256) sJ[i] = g_J[t0 * 26 + i];
        __syncthreads();

        float a[25], U[25];
        #pragma unroll
        for (int i = 0; i < 25; i++) { a[i] = Ain[i]; U[i] = g_U[i]; }

        float z0 = 0, z1 = 0, z2 = 0, z3 = 0, z4 = 0;
        double ll = 0.0;
        const int b = tid;
        const float* pj = &g_proj[((size_t)t0 * 6) * NB + b];

        for (int s = 0; s < nsteps; ++s) {
            float cc[5], syy;
            #pragma unroll
            for (int k = 0; k < 5; k++) cc[k] = pj[k * NB];
            syy = pj[5 * NB];
            pj += 6 * NB;

            float zp[5];
            #pragma unroll
            for (int i = 0; i < 5; i++)
                zp[i] = a[i * 5 + 0] * z0 + a[i * 5 + 1] * z1 + a[i * 5 + 2] * z2
                      + a[i * 5 + 3] * z3 + a[i * 5 + 4] * z4;
            float g[5];
            #pragma unroll
            for (int i = 0; i < 5; i++) {
                float sa = 0.f;
                #pragma unroll
                for (int j = 0; j < 5; j++) sa += U[i * 5 + j] * zp[j];
                g[i] = sa;
            }
            float w[5];
            #pragma unroll
            for (int i = 0; i < 5; i++) w[i] = cc[i] - g[i];
            const float* Jr = &sJ[s * 26];
            float h[5];
            #pragma unroll
            for (int i = 0; i < 5; i++) {
                float sa = 0.f;
                #pragma unroll
                for (int j = 0; j < 5; j++) sa += Jr[i * 5 + j] * w[j];
                h[i] = sa;
            }
            z0 = zp[0] + h[0]; z1 = zp[1] + h[1]; z2 = zp[2] + h[2];
            z3 = zp[3] + h[3]; z4 = zp[4] + h[4];

            if (s >= warm) {
                float cz = 0, zg = 0, wh = 0;
                #pragma unroll
                for (int i = 0; i < 5; i++) {
                    cz += cc[i] * zp[i]; zg += zp[i] * g[i]; wh += w[i] * h[i];
                }
                float quad = syy - 2.f * cz + zg - wh;
                ll -= 0.5 * ((double)OD * 1.8378770664093453
                             + (double)Jr[25] + (double)quad);

                int sl = (s - warm) & (Z_FLUSH - 1);
                float* sb = &sbuf[b * 41 + sl * 5];
                sb[0] = z0; sb[1] = z1; sb[2] = z2; sb[3] = z3; sb[4] = z4;
                if (sl == Z_FLUSH - 1) {
                    __syncthreads();
                    int tflush0 = town + ((s - warm) & ~(Z_FLUSH - 1));
                    for (int f = tid; f < NB * Z_FLUSH * 5; f += 256) {
                        int bb = f / (Z_FLUSH * 5);
                        int u  = f % (Z_FLUSH * 5);
                        out[OUT_STATES + ((size_t)bb * TT + tflush0) * 5 + u]
                            = sbuf[bb * 41 + u];
                    }
                    __syncthreads();
                }
            }
        }
        g_llpart[chunk * NB + b] = ll;
    } else {
        // ---- covariance broadcast: contiguous float4 runs per batch ----
        const int v = blockIdx.x - Z_NCHUNK;       // t-tile index, 0..255
        const int t0 = v * BC_TILE;
        float* sJ = sm;                            // 800 floats (16B aligned)
        for (int i = tid; i < BC_TILE * 25; i += 256) {
            int tt = i / 25;
            int e  = i % 25;
            sJ[i] = g_J[(t0 + tt) * 26 + e];
        }
        __syncthreads();
        const float4* sJ4 = (const float4*)sJ;     // 200 float4
        float4* out4 = (float4*)(out + OUT_COVS);
        const unsigned base = (unsigned)v * 200u;  // t0*25/4
        if (tid < 200) {
            float4 val = sJ4[tid];
            #pragma unroll 4
            for (int bb = 0; bb < NB; ++bb) {
                out4[(size_t)bb * (TT * 25 / 4) + base + tid] = val;
            }
        }
    }
}

// ============================================================================
// Kernel 4: deterministic ll reduction over z-chunks
// ============================================================================
__global__ void k_ll(float* __restrict__ out)
{
    int b = threadIdx.x;
    double s = 0.0;
    for (int c = 0; c < Z_NCHUNK; c++) s += g_llpart[c * NB + b];
    out[OUT_LL + b] = (float)s;
}

// ============================================================================
extern "C" void kernel_launch(void* const* d_in, const int* in_sizes, int n_in,
                              void* d_out, int out_size)
{
    const float* y  = (const float*)d_in[0];
    const float* A  = (const float*)d_in[1];
    const float* C  = (const float*)d_in[2];
    const float* Ql = (const float*)d_in[3];
    const float* Rl = (const float*)d_in[4];
    float* out = (float*)d_out;

    cudaFuncSetAttribute(k_zb, cudaFuncAttributeMaxDynamicSharedMemorySize, ZB_SMEM);

    k_ricc<<<R_NBLK, 32>>>(A, C, Ql, Rl);
    k_proj<<<P_NBLK, 256>>>(y, C, Rl);
    k_zb<<<Z_NCHUNK + BC_NBLK, 256, ZB_SMEM>>>(A, out);
    k_ll<<<1, 256>>>(out);
}

// round 4
// speedup vs baseline: 1.4735x; 1.1183x over previous
#include <cuda_runtime.h>
#include <math.h>

// Problem constants (fixed by the dataset)
#define SD 5
#define OD 32
#define NB 256
#define TT 8192

// ---------------- scratch (device globals; allocation-free) ----------------
// proj layout: [(t*6+k)*NB + b], k=0..4 -> (C^T R^-1 y)_k, k=5 -> y^T R^-1 y
__device__ float  g_proj[TT * 6 * NB];     // 50.3 MB
// J layout: [t*26 + e], e<25 = P_post (row-major), e=25 = logdet S_t
__device__ float  g_J[TT * 26];
__device__ float  g_U[25];                 // U = C^T R^-1 C
__device__ double g_llpart[128 * NB];      // per (z-chunk, batch) partial ll

// ---------------- Riccati config ----------------
#define R_LR 8
#define R_WR 24
#define R_NBLK 32                   // 32 blocks * 32 threads = 1024 chunks

// ---------------- z-recursion / broadcast config ----------------
#define Z_L 64
#define Z_W 64
#define Z_NCHUNK (TT / Z_L)         // 128
#define Z_MAXSTEPS (Z_L + Z_W)      // 128
#define Z_FLUSH 8
#define BC_TILE 32
#define BC_NBLK (TT / BC_TILE)      // 256
#define ZB_SMEM (Z_MAXSTEPS * 26 * 4 + NB * 41 * 4)   // 55296 B

// output offsets (tuple flattened: states, covs, ll)
#define OUT_STATES 0
#define OUT_COVS   ((size_t)NB * TT * SD)
#define OUT_LL     (OUT_COVS + (size_t)NB * TT * SD * SD)

// ============================================================================
// Kernel 1: data-independent Riccati recursion -> g_J, g_U
// ============================================================================
__global__ __launch_bounds__(32) void k_ricc(
    const float* __restrict__ Ain,
    const float* __restrict__ Cin,
    const float* __restrict__ Qlog,
    const float* __restrict__ Rlog)
{
    const int chunk = blockIdx.x * 32 + threadIdx.x;

    float a[25];
    #pragma unroll
    for (int i = 0; i < 25; i++) a[i] = Ain[i];
    float q[5];
    #pragma unroll
    for (int k = 0; k < 5; k++) q[k] = expf(Qlog[k]);

    float U[25];
    #pragma unroll
    for (int i = 0; i < 25; i++) U[i] = 0.f;
    float logdetR = 0.f;
    for (int o = 0; o < OD; o++) {
        float rl = Rlog[o];
        logdetR += rl;
        float ri = expf(-rl);
        float cv[5];
        #pragma unroll
        for (int k = 0; k < 5; k++) cv[k] = Cin[o * 5 + k];
        #pragma unroll
        for (int i = 0; i < 5; i++) {
            float f = ri * cv[i];
            #pragma unroll
            for (int j = 0; j < 5; j++) U[i * 5 + j] += f * cv[j];
        }
    }
    if (chunk == 0) {
        #pragma unroll
        for (int i = 0; i < 25; i++) g_U[i] = U[i];
    }

    const int town = chunk * R_LR;
    const int tend = town + R_LR;
    int t0s = town - R_WR; if (t0s < 0) t0s = 0;

    float P[25];
    #pragma unroll
    for (int i = 0; i < 25; i++) P[i] = (i % 6 == 0) ? 1.f : 0.f;

    for (int t = t0s; t < tend; ++t) {
        float Tm[25], Pp[25];
        #pragma unroll
        for (int i = 0; i < 5; i++)
            #pragma unroll
            for (int j = 0; j < 5; j++) {
                float s = 0.f;
                #pragma unroll
                for (int k = 0; k < 5; k++) s += a[i * 5 + k] * P[k * 5 + j];
                Tm[i * 5 + j] = s;
            }
        #pragma unroll
        for (int i = 0; i < 5; i++)
            #pragma unroll
            for (int j = 0; j < 5; j++) {
                float s = 0.f;
                #pragma unroll
                for (int k = 0; k < 5; k++) s += Tm[i * 5 + k] * a[j * 5 + k];
                Pp[i * 5 + j] = s;
            }
        #pragma unroll
        for (int i = 0; i < 5; i++) Pp[i * 5 + i] += q[i];

        // M = I + U*Pp ; pivotless Gauss-Jordan inverse (+det)
        float M[25], V[25];
        #pragma unroll
        for (int i = 0; i < 5; i++)
            #pragma unroll
            for (int j = 0; j < 5; j++) {
                float s = (i == j) ? 1.f : 0.f;
                #pragma unroll
                for (int k = 0; k < 5; k++) s += U[i * 5 + k] * Pp[k * 5 + j];
                M[i * 5 + j] = s;
            }
        #pragma unroll
        for (int i = 0; i < 25; i++) V[i] = (i % 6 == 0) ? 1.f : 0.f;
        float det = 1.f;
        #pragma unroll
        for (int k = 0; k < 5; k++) {
            float piv = M[k * 5 + k];
            det *= piv;
            float ip = 1.f / piv;
            #pragma unroll
            for (int j = 0; j < 5; j++) { M[k * 5 + j] *= ip; V[k * 5 + j] *= ip; }
            #pragma unroll
            for (int i2 = 0; i2 < 5; i2++) {
                if (i2 == k) continue;
                float f = M[i2 * 5 + k];
                #pragma unroll
                for (int j = 0; j < 5; j++) {
                    M[i2 * 5 + j] -= f * M[k * 5 + j];
                    V[i2 * 5 + j] -= f * V[k * 5 + j];
                }
            }
        }
        #pragma unroll
        for (int i = 0; i < 5; i++)
            #pragma unroll
            for (int j = 0; j < 5; j++) {
                float s = 0.f;
                #pragma unroll
                for (int k = 0; k < 5; k++) s += Pp[i * 5 + k] * V[k * 5 + j];
                P[i * 5 + j] = s;
            }

        if (t >= town) {
            float ld = logdetR + logf(det);
            #pragma unroll
            for (int e = 0; e < 25; e++) g_J[t * 26 + e] = P[e];
            g_J[t * 26 + 25] = ld;
        }
    }
}

// ============================================================================
// Kernel 2: observation projection y -> g_proj  (transpose through smem)
// Block = one time step x all 256 batches.
//  load:    f -> (b = f>>3, q = f&7); warp LDG.128 covers 4 fully-used lines
//  staging: sy[b*33 + ...] pad-33 -> conflict-free STS and LDS
//  compute: thread = b -> 6 coalesced proj stores
// ============================================================================
__global__ __launch_bounds__(256) void k_proj(
    const float* __restrict__ y,
    const float* __restrict__ Cin,
    const float* __restrict__ Rlog)
{
    __shared__ float sy[NB * 33];   // 33.8 KB
    __shared__ float crv[OD * 5];   // (C^T R^-1)[k][o] interleaved [o*5+k]
    __shared__ float rin[OD];
    const int tid = threadIdx.x;
    const int t = blockIdx.x;

    if (tid < OD * 5) {
        int o = tid / 5;
        crv[tid] = Cin[tid] * expf(-Rlog[o]);
    } else if (tid < OD * 5 + OD) {
        rin[tid - OD * 5] = expf(-Rlog[tid - OD * 5]);
    }

    const float4* y4 = (const float4*)y;
    #pragma unroll
    for (int it = 0; it < 8; ++it) {
        int f = it * 256 + tid;
        int b = f >> 3;
        int qq = f & 7;
        float4 v = y4[((size_t)b * TT + t) * 8 + qq];
        float* s = &sy[b * 33 + qq * 4];
        s[0] = v.x; s[1] = v.y; s[2] = v.z; s[3] = v.w;
    }
    __syncthreads();

    const int b = tid;
    const float* row = &sy[b * 33];
    float c0 = 0, c1 = 0, c2 = 0, c3 = 0, c4 = 0, syy = 0;
    #pragma unroll
    for (int o = 0; o < OD; o++) {
        float yv = row[o];
        syy += (yv * rin[o]) * yv;
        c0 += crv[o * 5 + 0] * yv;
        c1 += crv[o * 5 + 1] * yv;
        c2 += crv[o * 5 + 2] * yv;
        c3 += crv[o * 5 + 3] * yv;
        c4 += crv[o * 5 + 4] * yv;
    }
    float* pd = &g_proj[((size_t)t * 6) * NB + b];
    pd[0 * NB] = c0; pd[1 * NB] = c1; pd[2 * NB] = c2;
    pd[3 * NB] = c3; pd[4 * NB] = c4; pd[5 * NB] = syy;
}

// ============================================================================
// Kernel 3: (a) z-recursion + states + ll partials   [blocks 0..127]
//           (b) covariance broadcast J -> covs        [blocks 128..383]
// ============================================================================
__global__ __launch_bounds__(256) void k_zb(
    const float* __restrict__ Ain, float* __restrict__ out)
{
    extern __shared__ float sm[];
    const int tid = threadIdx.x;

    if (blockIdx.x < Z_NCHUNK) {
        float* sJ   = sm;                       // [nsteps][26]
        float* sbuf = sm + Z_MAXSTEPS * 26;     // [NB][41]

        const int chunk = blockIdx.x;
        const int town = chunk * Z_L;
        int t0 = town - Z_W; if (t0 < 0) t0 = 0;
        const int nsteps = town + Z_L - t0;
        const int warm = town - t0;

        for (int i = tid; i < nsteps * 26; i += 256) sJ[i] = g_J[t0 * 26 + i];
        __syncthreads();

        float a[25], U[25];
        #pragma unroll
        for (int i = 0; i < 25; i++) { a[i] = Ain[i]; U[i] = g_U[i]; }

        float z0 = 0, z1 = 0, z2 = 0, z3 = 0, z4 = 0;
        double ll = 0.0;
        const int b = tid;
        const float* pj = &g_proj[((size_t)t0 * 6) * NB + b];

        for (int s = 0; s < nsteps; ++s) {
            float cc[5], syy;
            #pragma unroll
            for (int k = 0; k < 5; k++) cc[k] = pj[k * NB];
            syy = pj[5 * NB];
            pj += 6 * NB;

            float zp[5];
            #pragma unroll
            for (int i = 0; i < 5; i++)
                zp[i] = a[i * 5 + 0] * z0 + a[i * 5 + 1] * z1 + a[i * 5 + 2] * z2
                      + a[i * 5 + 3] * z3 + a[i * 5 + 4] * z4;
            float g[5];
            #pragma unroll
            for (int i = 0; i < 5; i++) {
                float sa = 0.f;
                #pragma unroll
                for (int j = 0; j < 5; j++) sa += U[i * 5 + j] * zp[j];
                g[i] = sa;
            }
            float w[5];
            #pragma unroll
            for (int i = 0; i < 5; i++) w[i] = cc[i] - g[i];
            const float* Jr = &sJ[s * 26];
            float h[5];
            #pragma unroll
            for (int i = 0; i < 5; i++) {
                float sa = 0.f;
                #pragma unroll
                for (int j = 0; j < 5; j++) sa += Jr[i * 5 + j] * w[j];
                h[i] = sa;
            }
            z0 = zp[0] + h[0]; z1 = zp[1] + h[1]; z2 = zp[2] + h[2];
            z3 = zp[3] + h[3]; z4 = zp[4] + h[4];

            if (s >= warm) {
                float cz = 0, zg = 0, wh = 0;
                #pragma unroll
                for (int i = 0; i < 5; i++) {
                    cz += cc[i] * zp[i]; zg += zp[i] * g[i]; wh += w[i] * h[i];
                }
                float quad = syy - 2.f * cz + zg - wh;
                ll -= 0.5 * ((double)OD * 1.8378770664093453
                             + (double)Jr[25] + (double)quad);

                int sl = (s - warm) & (Z_FLUSH - 1);
                float* sb = &sbuf[b * 41 + sl * 5];
                sb[0] = z0; sb[1] = z1; sb[2] = z2; sb[3] = z3; sb[4] = z4;
                if (sl == Z_FLUSH - 1) {
                    __syncthreads();
                    int tflush0 = town + ((s - warm) & ~(Z_FLUSH - 1));
                    for (int f = tid; f < NB * Z_FLUSH * 5; f += 256) {
                        int bb = f / (Z_FLUSH * 5);
                        int u  = f % (Z_FLUSH * 5);
                        __stcs(&out[OUT_STATES + ((size_t)bb * TT + tflush0) * 5 + u],
                               sbuf[bb * 41 + u]);
                    }
                    __syncthreads();
                }
            }
        }
        g_llpart[chunk * NB + b] = ll;
    } else {
        // ---- covariance broadcast: contiguous float4 streaming stores ----
        const int v = blockIdx.x - Z_NCHUNK;       // t-tile index, 0..255
        const int t0 = v * BC_TILE;
        float* sJ = sm;                            // 800 floats
        for (int i = tid; i < BC_TILE * 25; i += 256) {
            int tt = i / 25;
            int e  = i % 25;
            sJ[i] = g_J[(t0 + tt) * 26 + e];
        }
        __syncthreads();
        const float4* sJ4 = (const float4*)sJ;     // 200 float4
        float4* out4 = (float4*)(out + OUT_COVS);
        const unsigned base = (unsigned)v * 200u;
        if (tid < 200) {
            float4 val = sJ4[tid];
            #pragma unroll 4
            for (int bb = 0; bb < NB; ++bb) {
                __stcs(&out4[(size_t)bb * (TT * 25 / 4) + base + tid], val);
            }
        }
    }
}

// ============================================================================
// Kernel 4: ll reduction — 16 blocks x 128 thr, shuffle-reduce groups of 8
// thread t: b = blk*16 + t/8, chunk range [(t%8)*16, +16)
// ============================================================================
__global__ __launch_bounds__(128) void k_ll(float* __restrict__ out)
{
    const int tid = threadIdx.x;
    const int b = blockIdx.x * 16 + (tid >> 3);
    const int c0 = (tid & 7) * 16;
    double s = 0.0;
    #pragma unroll
    for (int c = 0; c < 16; c++) s += g_llpart[(c0 + c) * NB + b];
    // reduce across the 8-lane group (same b)
    #pragma unroll
    for (int d = 1; d < 8; d <<= 1)
        s += __shfl_xor_sync(0xFFFFFFFFu, s, d);
    if ((tid & 7) == 0) out[OUT_LL + b] = (float)s;
}

// ============================================================================
extern "C" void kernel_launch(void* const* d_in, const int* in_sizes, int n_in,
                              void* d_out, int out_size)
{
    const float* y  = (const float*)d_in[0];
    const float* A  = (const float*)d_in[1];
    const float* C  = (const float*)d_in[2];
    const float* Ql = (const float*)d_in[3];
    const float* Rl = (const float*)d_in[4];
    float* out = (float*)d_out;

    cudaFuncSetAttribute(k_zb, cudaFuncAttributeMaxDynamicSharedMemorySize, ZB_SMEM);

    k_ricc<<<R_NBLK, 32>>>(A, C, Ql, Rl);
    k_proj<<<TT, 256>>>(y, C, Rl);
    k_zb<<<Z_NCHUNK + BC_NBLK, 256, ZB_SMEM>>>(A, out);
    k_ll<<<16, 128>>>(out);
}

// round 5
// speedup vs baseline: 1.8975x; 1.2878x over previous
#include <cuda_runtime.h>
#include <math.h>

// Problem constants (fixed by the dataset)
#define SD 5
#define OD 32
#define NB 256
#define TT 8192

// ---------------- scratch (device globals; allocation-free) ----------------
// proj layout: [(t*6+k)*NB + b], k=0..4 -> (C^T R^-1 y)_k, k=5 -> y^T R^-1 y
__device__ float  g_proj[TT * 6 * NB];     // 50.3 MB
// J layout: [t*26 + e], e<25 = P_post (row-major), e=25 = logdet S_t
__device__ float  g_J[TT * 26];
__device__ float  g_U[25];                 // U = C^T R^-1 C
__device__ double g_llpart[NB * 256];      // [b][chunk] partial ll (b-major)

// ---------------- Riccati config ----------------
#define R_LR 8
#define R_WR 24
#define R_NBLK 32                   // 1024 chunks

// ---------------- projection config ----------------
#define P_TT 2                      // time steps per proj block
#define P_SMEM (P_TT * NB * 33 * 4) // 67584 B

// ---------------- z-recursion / broadcast config ----------------
#define Z_L 32
#define Z_W 48
#define Z_NCHUNK (TT / Z_L)         // 256
#define Z_MAXSTEPS (Z_L + Z_W)      // 80
#define BC_TILE 32
#define BC_NBLK (TT / BC_TILE)      // 256
#define ZB_SMEM (Z_MAXSTEPS * 26 * 4 + NB * 41 * 4)   // 50304 B

// output offsets (tuple flattened: states, covs, ll)
#define OUT_STATES 0
#define OUT_COVS   ((size_t)NB * TT * SD)
#define OUT_LL     (OUT_COVS + (size_t)NB * TT * SD * SD)

// ============================================================================
// Kernel 1: data-independent Riccati recursion -> g_J, g_U
// ============================================================================
__global__ __launch_bounds__(32) void k_ricc(
    const float* __restrict__ Ain,
    const float* __restrict__ Cin,
    const float* __restrict__ Qlog,
    const float* __restrict__ Rlog)
{
    const int chunk = blockIdx.x * 32 + threadIdx.x;

    float a[25];
    #pragma unroll
    for (int i = 0; i < 25; i++) a[i] = Ain[i];
    float q[5];
    #pragma unroll
    for (int k = 0; k < 5; k++) q[k] = expf(Qlog[k]);

    float U[25];
    #pragma unroll
    for (int i = 0; i < 25; i++) U[i] = 0.f;
    float logdetR = 0.f;
    for (int o = 0; o < OD; o++) {
        float rl = Rlog[o];
        logdetR += rl;
        float ri = expf(-rl);
        float cv[5];
        #pragma unroll
        for (int k = 0; k < 5; k++) cv[k] = Cin[o * 5 + k];
        #pragma unroll
        for (int i = 0; i < 5; i++) {
            float f = ri * cv[i];
            #pragma unroll
            for (int j = 0; j < 5; j++) U[i * 5 + j] += f * cv[j];
        }
    }
    if (chunk == 0) {
        #pragma unroll
        for (int i = 0; i < 25; i++) g_U[i] = U[i];
    }

    const int town = chunk * R_LR;
    const int tend = town + R_LR;
    int t0s = town - R_WR; if (t0s < 0) t0s = 0;

    float P[25];
    #pragma unroll
    for (int i = 0; i < 25; i++) P[i] = (i % 6 == 0) ? 1.f : 0.f;

    for (int t = t0s; t < tend; ++t) {
        float Tm[25], Pp[25];
        #pragma unroll
        for (int i = 0; i < 5; i++)
            #pragma unroll
            for (int j = 0; j < 5; j++) {
                float s = 0.f;
                #pragma unroll
                for (int k = 0; k < 5; k++) s += a[i * 5 + k] * P[k * 5 + j];
                Tm[i * 5 + j] = s;
            }
        #pragma unroll
        for (int i = 0; i < 5; i++)
            #pragma unroll
            for (int j = 0; j < 5; j++) {
                float s = 0.f;
                #pragma unroll
                for (int k = 0; k < 5; k++) s += Tm[i * 5 + k] * a[j * 5 + k];
                Pp[i * 5 + j] = s;
            }
        #pragma unroll
        for (int i = 0; i < 5; i++) Pp[i * 5 + i] += q[i];

        // M = I + U*Pp ; pivotless Gauss-Jordan inverse (+det)
        float M[25], V[25];
        #pragma unroll
        for (int i = 0; i < 5; i++)
            #pragma unroll
            for (int j = 0; j < 5; j++) {
                float s = (i == j) ? 1.f : 0.f;
                #pragma unroll
                for (int k = 0; k < 5; k++) s += U[i * 5 + k] * Pp[k * 5 + j];
                M[i * 5 + j] = s;
            }
        #pragma unroll
        for (int i = 0; i < 25; i++) V[i] = (i % 6 == 0) ? 1.f : 0.f;
        float det = 1.f;
        #pragma unroll
        for (int k = 0; k < 5; k++) {
            float piv = M[k * 5 + k];
            det *= piv;
            float ip = 1.f / piv;
            #pragma unroll
            for (int j = 0; j < 5; j++) { M[k * 5 + j] *= ip; V[k * 5 + j] *= ip; }
            #pragma unroll
            for (int i2 = 0; i2 < 5; i2++) {
                if (i2 == k) continue;
                float f = M[i2 * 5 + k];
                #pragma unroll
                for (int j = 0; j < 5; j++) {
                    M[i2 * 5 + j] -= f * M[k * 5 + j];
                    V[i2 * 5 + j] -= f * V[k * 5 + j];
                }
            }
        }
        #pragma unroll
        for (int i = 0; i < 5; i++)
            #pragma unroll
            for (int j = 0; j < 5; j++) {
                float s = 0.f;
                #pragma unroll
                for (int k = 0; k < 5; k++) s += Pp[i * 5 + k] * V[k * 5 + j];
                P[i * 5 + j] = s;
            }

        if (t >= town) {
            float ld = logdetR + logf(det);
            #pragma unroll
            for (int e = 0; e < 25; e++) g_J[t * 26 + e] = P[e];
            g_J[t * 26 + 25] = ld;
        }
    }
}

// ============================================================================
// Kernel 2: observation projection y -> g_proj
// Block = 2 consecutive time steps x all 256 batches.
//  load: warp reads 256B contiguous per batch row (better DRAM locality),
//        __ldcs streaming so proj writes stay L2-resident for k_zb.
// ============================================================================
__global__ __launch_bounds__(256) void k_proj(
    const float* __restrict__ y,
    const float* __restrict__ Cin,
    const float* __restrict__ Rlog)
{
    extern __shared__ float sy[];   // [P_TT][NB][33]
    __shared__ float crv[OD * 5];
    __shared__ float rin[OD];
    const int tid = threadIdx.x;
    const int t0 = blockIdx.x * P_TT;

    if (tid < OD * 5) {
        int o = tid / 5;
        crv[tid] = Cin[tid] * expf(-Rlog[o]);
    } else if (tid < OD * 5 + OD) {
        rin[tid - OD * 5] = expf(-Rlog[tid - OD * 5]);
    }

    const float4* y4 = (const float4*)y;
    #pragma unroll
    for (int it = 0; it < 2 * NB * 8 / 256; ++it) {  // 16 iters
        int f = it * 256 + tid;
        int qq = f & 7;
        int tt = (f >> 3) & (P_TT - 1);
        int b  = f >> 4;
        float4 v = __ldcs(&y4[((size_t)b * TT + t0 + tt) * 8 + qq]);
        float* s = &sy[(tt * NB + b) * 33 + qq * 4];
        s[0] = v.x; s[1] = v.y; s[2] = v.z; s[3] = v.w;
    }
    __syncthreads();

    const int b = tid;
    #pragma unroll
    for (int tt = 0; tt < P_TT; ++tt) {
        const float* row = &sy[(tt * NB + b) * 33];
        float c0 = 0, c1 = 0, c2 = 0, c3 = 0, c4 = 0, syy = 0;
        #pragma unroll
        for (int o = 0; o < OD; o++) {
            float yv = row[o];
            syy += (yv * rin[o]) * yv;
            c0 += crv[o * 5 + 0] * yv;
            c1 += crv[o * 5 + 1] * yv;
            c2 += crv[o * 5 + 2] * yv;
            c3 += crv[o * 5 + 3] * yv;
            c4 += crv[o * 5 + 4] * yv;
        }
        float* pd = &g_proj[((size_t)(t0 + tt) * 6) * NB + b];
        pd[0 * NB] = c0; pd[1 * NB] = c1; pd[2 * NB] = c2;
        pd[3 * NB] = c3; pd[4 * NB] = c4; pd[5 * NB] = syy;
    }
}

// ---------------- one z step (inlined helper via macro-free lambda) --------
#define Z_STEP(CCBUF, U_)                                                     \
    {                                                                         \
        float zp[5];                                                          \
        _Pragma("unroll")                                                     \
        for (int i = 0; i < 5; i++)                                           \
            zp[i] = a[i*5+0]*z0 + a[i*5+1]*z1 + a[i*5+2]*z2                   \
                  + a[i*5+3]*z3 + a[i*5+4]*z4;                                \
        float g[5];                                                           \
        _Pragma("unroll")                                                     \
        for (int i = 0; i < 5; i++) {                                         \
            float sa = 0.f;                                                   \
            _Pragma("unroll")                                                 \
            for (int j = 0; j < 5; j++) sa += U_[i*5+j] * zp[j];              \
            g[i] = sa;                                                        \
        }                                                                     \
        float w[5];                                                           \
        _Pragma("unroll")                                                     \
        for (int i = 0; i < 5; i++) w[i] = (CCBUF)[i] - g[i];                 \
        const float* Jr = &sJ[s * 26];                                        \
        float h[5];                                                           \
        _Pragma("unroll")                                                     \
        for (int i = 0; i < 5; i++) {                                         \
            float sa = 0.f;                                                   \
            _Pragma("unroll")                                                 \
            for (int j = 0; j < 5; j++) sa += Jr[i*5+j] * w[j];               \
            h[i] = sa;                                                        \
        }                                                                     \
        z0 = zp[0]+h[0]; z1 = zp[1]+h[1]; z2 = zp[2]+h[2];                    \
        z3 = zp[3]+h[3]; z4 = zp[4]+h[4];                                     \
        if (s >= warm) {                                                      \
            float cz = 0, zg = 0, wh = 0;                                     \
            _Pragma("unroll")                                                 \
            for (int i = 0; i < 5; i++) {                                     \
                cz += (CCBUF)[i]*zp[i]; zg += zp[i]*g[i]; wh += w[i]*h[i];    \
            }                                                                 \
            float quad = (CCBUF)[5] - 2.f*cz + zg - wh;                       \
            ll -= 0.5 * ((double)OD * 1.8378770664093453                      \
                         + (double)Jr[25] + (double)quad);                    \
            int sl = (s - warm) & 7;                                          \
            float* sb = &sbuf[b * 41 + sl * 5];                               \
            sb[0]=z0; sb[1]=z1; sb[2]=z2; sb[3]=z3; sb[4]=z4;                 \
        }                                                                     \
    }

// ============================================================================
// Kernel 3: (a) z-recursion + states + ll partials   [blocks 0..255]
//           (b) covariance broadcast J -> covs        [blocks 256..511]
// z-part uses an explicit 4-step ping-pong register prefetch pipeline.
// ============================================================================
__global__ __launch_bounds__(256) void k_zb(
    const float* __restrict__ Ain, float* __restrict__ out)
{
    extern __shared__ float sm[];
    const int tid = threadIdx.x;

    if (blockIdx.x < Z_NCHUNK) {
        float* sJ   = sm;                         // [Z_MAXSTEPS][26]
        float* sbuf = sm + Z_MAXSTEPS * 26;       // [NB][41]

        const int chunk = blockIdx.x;
        const int town = chunk * Z_L;
        int t0 = town - Z_W; if (t0 < 0) t0 = 0;
        const int nsteps = town + Z_L - t0;       // 32 or 80 (both %8==0)
        const int warm = town - t0;               // 0 or 48

        for (int i = tid; i < nsteps * 26; i += 256) sJ[i] = g_J[t0 * 26 + i];
        __syncthreads();

        float a[25], U[25];
        #pragma unroll
        for (int i = 0; i < 25; i++) { a[i] = Ain[i]; U[i] = g_U[i]; }

        float z0 = 0, z1 = 0, z2 = 0, z3 = 0, z4 = 0;
        double ll = 0.0;
        const int b = tid;
        const float* pbase = &g_proj[(size_t)t0 * 6 * NB + b];

        float bufA[4][6], bufB[4][6];
        // prologue: steps 0..3 into bufA
        #pragma unroll
        for (int u = 0; u < 4; u++)
            #pragma unroll
            for (int k = 0; k < 6; k++)
                bufA[u][k] = pbase[((size_t)u * 6 + k) * NB];

        for (int s8 = 0; s8 < nsteps; s8 += 8) {
            // prefetch steps s8+4..s8+7 into bufB
            if (s8 + 4 < nsteps) {
                const float* pn = pbase + (size_t)(s8 + 4) * 6 * NB;
                #pragma unroll
                for (int u = 0; u < 4; u++)
                    #pragma unroll
                    for (int k = 0; k < 6; k++)
                        bufB[u][k] = pn[((size_t)u * 6 + k) * NB];
            }
            // compute steps s8..s8+3 from bufA
            #pragma unroll
            for (int u = 0; u < 4; u++) {
                const int s = s8 + u;
                Z_STEP(bufA[u], U)
            }
            // prefetch steps s8+8..s8+11 into bufA
            if (s8 + 8 < nsteps) {
                const float* pn = pbase + (size_t)(s8 + 8) * 6 * NB;
                #pragma unroll
                for (int u = 0; u < 4; u++)
                    #pragma unroll
                    for (int k = 0; k < 6; k++)
                        bufA[u][k] = pn[((size_t)u * 6 + k) * NB];
            }
            // compute steps s8+4..s8+7 from bufB
            #pragma unroll
            for (int u = 0; u < 4; u++) {
                const int s = s8 + 4 + u;
                Z_STEP(bufB[u], U)
            }
            // flush the 8 owned states (warm is a multiple of 8)
            if (s8 >= warm) {
                __syncthreads();
                const int tflush0 = town + (s8 - warm);
                for (int f = tid; f < NB * 40; f += 256) {
                    int bb = f / 40;
                    int u  = f % 40;
                    __stcs(&out[OUT_STATES + ((size_t)bb * TT + tflush0) * 5 + u],
                           sbuf[bb * 41 + u]);
                }
                __syncthreads();
            }
        }
        g_llpart[(size_t)b * Z_NCHUNK + chunk] = ll;
    } else {
        // ---- covariance broadcast: contiguous float4 streaming stores ----
        const int v = blockIdx.x - Z_NCHUNK;       // 0..255
        const int t0 = v * BC_TILE;
        float* sJ = sm;                            // 800 floats
        for (int i = tid; i < BC_TILE * 25; i += 256) {
            int tt = i / 25;
            int e  = i % 25;
            sJ[i] = g_J[(t0 + tt) * 26 + e];
        }
        __syncthreads();
        const float4* sJ4 = (const float4*)sJ;     // 200 float4
        float4* out4 = (float4*)(out + OUT_COVS);
        const unsigned base = (unsigned)v * 200u;
        if (tid < 200) {
            float4 val = sJ4[tid];
            #pragma unroll 4
            for (int bb = 0; bb < NB; ++bb) {
                __stcs(&out4[(size_t)bb * (TT * 25 / 4) + base + tid], val);
            }
        }
    }
}

// ============================================================================
// Kernel 4: ll reduction — thread = one batch, contiguous 256-double run
// ============================================================================
__global__ __launch_bounds__(128) void k_ll(float* __restrict__ out)
{
    const int b = blockIdx.x * 128 + threadIdx.x;
    const double2* p = (const double2*)&g_llpart[(size_t)b * Z_NCHUNK];
    double s = 0.0;
    #pragma unroll 8
    for (int c = 0; c < Z_NCHUNK / 2; c++) {
        double2 v = p[c];
        s += v.x + v.y;
    }
    out[OUT_LL + b] = (float)s;
}

// ============================================================================
extern "C" void kernel_launch(void* const* d_in, const int* in_sizes, int n_in,
                              void* d_out, int out_size)
{
    const float* y  = (const float*)d_in[0];
    const float* A  = (const float*)d_in[1];
    const float* C  = (const float*)d_in[2];
    const float* Ql = (const float*)d_in[3];
    const float* Rl = (const float*)d_in[4];
    float* out = (float*)d_out;

    cudaFuncSetAttribute(k_proj, cudaFuncAttributeMaxDynamicSharedMemorySize, P_SMEM);
    cudaFuncSetAttribute(k_zb, cudaFuncAttributeMaxDynamicSharedMemorySize, ZB_SMEM);

    k_ricc<<<R_NBLK, 32>>>(A, C, Ql, Rl);
    k_proj<<<TT / P_TT, 256, P_SMEM>>>(y, C, Rl);
    k_zb<<<Z_NCHUNK + BC_NBLK, 256, ZB_SMEM>>>(A, out);
    k_ll<<<2, 128>>>(out);
}

// round 6
// speedup vs baseline: 2.0723x; 1.0921x over previous
#include <cuda_runtime.h>
#include <math.h>

// Problem constants (fixed by the dataset)
#define SD 5
#define OD 32
#define NB 256
#define TT 8192

// ---------------- scratch (device globals; allocation-free) ----------------
// proj layout: [(t*6+k)*NB + b], k=0..4 -> (C^T R^-1 y)_k, k=5 -> y^T R^-1 y
__device__ float  g_proj[TT * 6 * NB];     // 50.3 MB
// J layout: [t*26 + e], e<25 = P_post (row-major), e=25 = logdet S_t
__device__ float  g_J[TT * 26];
__device__ float  g_U[25];                 // U = C^T R^-1 C
__device__ double g_llpart[NB * 256];      // [b][chunk] partial ll (b-major)

// ---------------- Riccati config ----------------
#define R_LR 8
#define R_WR 24
#define R_NBLK 32                   // 1024 chunks

// ---------------- projection + covs-broadcast config ----------------
#define P_TT 2                      // time steps per proj block
#define P_NBLK (TT / P_TT)          // 4096
#define BC_TILE 32
#define BC_NBLK (TT / BC_TILE)      // 256
#define P_SMEM (P_TT * NB * 33 * 4) // 67584 B

// ---------------- z-recursion config ----------------
#define Z_L 32
#define Z_W 48
#define Z_NCHUNK (TT / Z_L)         // 256
#define Z_MAXSTEPS (Z_L + Z_W)      // 80
#define ZB_SMEM (Z_MAXSTEPS * 26 * 4 + NB * 41 * 4)   // 50304 B

// output offsets (tuple flattened: states, covs, ll)
#define OUT_STATES 0
#define OUT_COVS   ((size_t)NB * TT * SD)
#define OUT_LL     (OUT_COVS + (size_t)NB * TT * SD * SD)

// ============================================================================
// Kernel 1: data-independent Riccati recursion -> g_J, g_U
// ============================================================================
__global__ __launch_bounds__(32) void k_ricc(
    const float* __restrict__ Ain,
    const float* __restrict__ Cin,
    const float* __restrict__ Qlog,
    const float* __restrict__ Rlog)
{
    const int chunk = blockIdx.x * 32 + threadIdx.x;

    float a[25];
    #pragma unroll
    for (int i = 0; i < 25; i++) a[i] = Ain[i];
    float q[5];
    #pragma unroll
    for (int k = 0; k < 5; k++) q[k] = expf(Qlog[k]);

    float U[25];
    #pragma unroll
    for (int i = 0; i < 25; i++) U[i] = 0.f;
    float logdetR = 0.f;
    for (int o = 0; o < OD; o++) {
        float rl = Rlog[o];
        logdetR += rl;
        float ri = expf(-rl);
        float cv[5];
        #pragma unroll
        for (int k = 0; k < 5; k++) cv[k] = Cin[o * 5 + k];
        #pragma unroll
        for (int i = 0; i < 5; i++) {
            float f = ri * cv[i];
            #pragma unroll
            for (int j = 0; j < 5; j++) U[i * 5 + j] += f * cv[j];
        }
    }
    if (chunk == 0) {
        #pragma unroll
        for (int i = 0; i < 25; i++) g_U[i] = U[i];
    }

    const int town = chunk * R_LR;
    const int tend = town + R_LR;
    int t0s = town - R_WR; if (t0s < 0) t0s = 0;

    float P[25];
    #pragma unroll
    for (int i = 0; i < 25; i++) P[i] = (i % 6 == 0) ? 1.f : 0.f;

    for (int t = t0s; t < tend; ++t) {
        float Tm[25], Pp[25];
        #pragma unroll
        for (int i = 0; i < 5; i++)
            #pragma unroll
            for (int j = 0; j < 5; j++) {
                float s = 0.f;
                #pragma unroll
                for (int k = 0; k < 5; k++) s += a[i * 5 + k] * P[k * 5 + j];
                Tm[i * 5 + j] = s;
            }
        #pragma unroll
        for (int i = 0; i < 5; i++)
            #pragma unroll
            for (int j = 0; j < 5; j++) {
                float s = 0.f;
                #pragma unroll
                for (int k = 0; k < 5; k++) s += Tm[i * 5 + k] * a[j * 5 + k];
                Pp[i * 5 + j] = s;
            }
        #pragma unroll
        for (int i = 0; i < 5; i++) Pp[i * 5 + i] += q[i];

        float M[25], V[25];
        #pragma unroll
        for (int i = 0; i < 5; i++)
            #pragma unroll
            for (int j = 0; j < 5; j++) {
                float s = (i == j) ? 1.f : 0.f;
                #pragma unroll
                for (int k = 0; k < 5; k++) s += U[i * 5 + k] * Pp[k * 5 + j];
                M[i * 5 + j] = s;
            }
        #pragma unroll
        for (int i = 0; i < 25; i++) V[i] = (i % 6 == 0) ? 1.f : 0.f;
        float det = 1.f;
        #pragma unroll
        for (int k = 0; k < 5; k++) {
            float piv = M[k * 5 + k];
            det *= piv;
            float ip = 1.f / piv;
            #pragma unroll
            for (int j = 0; j < 5; j++) { M[k * 5 + j] *= ip; V[k * 5 + j] *= ip; }
            #pragma unroll
            for (int i2 = 0; i2 < 5; i2++) {
                if (i2 == k) continue;
                float f = M[i2 * 5 + k];
                #pragma unroll
                for (int j = 0; j < 5; j++) {
                    M[i2 * 5 + j] -= f * M[k * 5 + j];
                    V[i2 * 5 + j] -= f * V[k * 5 + j];
                }
            }
        }
        #pragma unroll
        for (int i = 0; i < 5; i++)
            #pragma unroll
            for (int j = 0; j < 5; j++) {
                float s = 0.f;
                #pragma unroll
                for (int k = 0; k < 5; k++) s += Pp[i * 5 + k] * V[k * 5 + j];
                P[i * 5 + j] = s;
            }

        if (t >= town) {
            float ld = logdetR + logf(det);
            #pragma unroll
            for (int e = 0; e < 25; e++) g_J[t * 26 + e] = P[e];
            g_J[t * 26 + 25] = ld;
        }
    }
}

// ============================================================================
// Kernel 2: fused  (a) covariance broadcast J -> covs   [blocks 0..255]
//                  (b) observation projection y -> g_proj [blocks 256..4351]
// Both are low-register pure-streaming paths -> they share the LTS/HBM pipe.
// ============================================================================
__global__ __launch_bounds__(256) void k_projbc(
    const float* __restrict__ y,
    const float* __restrict__ Cin,
    const float* __restrict__ Rlog,
    float* __restrict__ out)
{
    extern __shared__ float sm[];
    const int tid = threadIdx.x;

    if (blockIdx.x < BC_NBLK) {
        // ---- covariance broadcast: contiguous float4 streaming stores ----
        const int v = blockIdx.x;                  // 0..255
        const int t0 = v * BC_TILE;
        float* sJ = sm;                            // 800 floats
        for (int i = tid; i < BC_TILE * 25; i += 256) {
            int tt = i / 25;
            int e  = i % 25;
            sJ[i] = g_J[(t0 + tt) * 26 + e];
        }
        __syncthreads();
        const float4* sJ4 = (const float4*)sJ;     // 200 float4
        float4* out4 = (float4*)(out + OUT_COVS);
        const unsigned base = (unsigned)v * 200u;
        if (tid < 200) {
            float4 val = sJ4[tid];
            #pragma unroll 4
            for (int bb = 0; bb < NB; ++bb) {
                __stcs(&out4[(size_t)bb * (TT * 25 / 4) + base + tid], val);
            }
        }
    } else {
        // ---- projection: 2 time steps x all 256 batches ----
        float* sy = sm;                 // [P_TT][NB][33]
        __shared__ float crv[OD * 5];
        __shared__ float rin[OD];
        const int t0 = (blockIdx.x - BC_NBLK) * P_TT;

        if (tid < OD * 5) {
            int o = tid / 5;
            crv[tid] = Cin[tid] * expf(-Rlog[o]);
        } else if (tid < OD * 5 + OD) {
            rin[tid - OD * 5] = expf(-Rlog[tid - OD * 5]);
        }

        const float4* y4 = (const float4*)y;
        #pragma unroll
        for (int it = 0; it < 2 * NB * 8 / 256; ++it) {  // 16 iters
            int f = it * 256 + tid;
            int qq = f & 7;
            int tt = (f >> 3) & (P_TT - 1);
            int b  = f >> 4;
            float4 v = __ldcs(&y4[((size_t)b * TT + t0 + tt) * 8 + qq]);
            float* s = &sy[(tt * NB + b) * 33 + qq * 4];
            s[0] = v.x; s[1] = v.y; s[2] = v.z; s[3] = v.w;
        }
        __syncthreads();

        const int b = tid;
        #pragma unroll
        for (int tt = 0; tt < P_TT; ++tt) {
            const float* row = &sy[(tt * NB + b) * 33];
            float c0 = 0, c1 = 0, c2 = 0, c3 = 0, c4 = 0, syy = 0;
            #pragma unroll
            for (int o = 0; o < OD; o++) {
                float yv = row[o];
                syy += (yv * rin[o]) * yv;
                c0 += crv[o * 5 + 0] * yv;
                c1 += crv[o * 5 + 1] * yv;
                c2 += crv[o * 5 + 2] * yv;
                c3 += crv[o * 5 + 3] * yv;
                c4 += crv[o * 5 + 4] * yv;
            }
            float* pd = &g_proj[((size_t)(t0 + tt) * 6) * NB + b];
            pd[0 * NB] = c0; pd[1 * NB] = c1; pd[2 * NB] = c2;
            pd[3 * NB] = c3; pd[4 * NB] = c4; pd[5 * NB] = syy;
        }
    }
}

// ---------------- one z step ----------------
#define Z_STEP(CCBUF, U_)                                                     \
    {                                                                         \
        float zp[5];                                                          \
        _Pragma("unroll")                                                     \
        for (int i = 0; i < 5; i++)                                           \
            zp[i] = a[i*5+0]*z0 + a[i*5+1]*z1 + a[i*5+2]*z2                   \
                  + a[i*5+3]*z3 + a[i*5+4]*z4;                                \
        float g[5];                                                           \
        _Pragma("unroll")                                                     \
        for (int i = 0; i < 5; i++) {                                         \
            float sa = 0.f;                                                   \
            _Pragma("unroll")                                                 \
            for (int j = 0; j < 5; j++) sa += U_[i*5+j] * zp[j];              \
            g[i] = sa;                                                        \
        }                                                                     \
        float w[5];                                                           \
        _Pragma("unroll")                                                     \
        for (int i = 0; i < 5; i++) w[i] = (CCBUF)[i] - g[i];                 \
        const float* Jr = &sJ[s * 26];                                        \
        float h[5];                                                           \
        _Pragma("unroll")                                                     \
        for (int i = 0; i < 5; i++) {                                         \
            float sa = 0.f;                                                   \
            _Pragma("unroll")                                                 \
            for (int j = 0; j < 5; j++) sa += Jr[i*5+j] * w[j];               \
            h[i] = sa;                                                        \
        }                                                                     \
        z0 = zp[0]+h[0]; z1 = zp[1]+h[1]; z2 = zp[2]+h[2];                    \
        z3 = zp[3]+h[3]; z4 = zp[4]+h[4];                                     \
        if (s >= warm) {                                                      \
            float cz = 0, zg = 0, wh = 0;                                     \
            _Pragma("unroll")                                                 \
            for (int i = 0; i < 5; i++) {                                     \
                cz += (CCBUF)[i]*zp[i]; zg += zp[i]*g[i]; wh += w[i]*h[i];    \
            }                                                                 \
            float quad = (CCBUF)[5] - 2.f*cz + zg - wh;                       \
            ll -= 0.5 * ((double)OD * 1.8378770664093453                      \
                         + (double)Jr[25] + (double)quad);                    \
            int sl = (s - warm) & 7;                                          \
            float* sb = &sbuf[b * 41 + sl * 5];                               \
            sb[0]=z0; sb[1]=z1; sb[2]=z2; sb[3]=z3; sb[4]=z4;                 \
        }                                                                     \
    }

// ============================================================================
// Kernel 3: z-recursion + states + ll partials (256 chunks, whole machine)
// Explicit 4-step ping-pong register prefetch pipeline; proj reads hit L2.
// ============================================================================
__global__ __launch_bounds__(256) void k_z(
    const float* __restrict__ Ain, float* __restrict__ out)
{
    extern __shared__ float sm[];
    const int tid = threadIdx.x;
    float* sJ   = sm;                         // [Z_MAXSTEPS][26]
    float* sbuf = sm + Z_MAXSTEPS * 26;       // [NB][41]

    const int chunk = blockIdx.x;
    const int town = chunk * Z_L;
    int t0 = town - Z_W; if (t0 < 0) t0 = 0;
    const int nsteps = town + Z_L - t0;       // 32 or 80 (both %8==0)
    const int warm = town - t0;               // 0 or 48

    for (int i = tid; i < nsteps * 26; i += 256) sJ[i] = g_J[t0 * 26 + i];
    __syncthreads();

    float a[25], U[25];
    #pragma unroll
    for (int i = 0; i < 25; i++) { a[i] = Ain[i]; U[i] = g_U[i]; }

    float z0 = 0, z1 = 0, z2 = 0, z3 = 0, z4 = 0;
    double ll = 0.0;
    const int b = tid;
    const float* pbase = &g_proj[(size_t)t0 * 6 * NB + b];

    float bufA[4][6], bufB[4][6];
    #pragma unroll
    for (int u = 0; u < 4; u++)
        #pragma unroll
        for (int k = 0; k < 6; k++)
            bufA[u][k] = pbase[((size_t)u * 6 + k) * NB];

    for (int s8 = 0; s8 < nsteps; s8 += 8) {
        if (s8 + 4 < nsteps) {
            const float* pn = pbase + (size_t)(s8 + 4) * 6 * NB;
            #pragma unroll
            for (int u = 0; u < 4; u++)
                #pragma unroll
                for (int k = 0; k < 6; k++)
                    bufB[u][k] = pn[((size_t)u * 6 + k) * NB];
        }
        #pragma unroll
        for (int u = 0; u < 4; u++) {
            const int s = s8 + u;
            Z_STEP(bufA[u], U)
        }
        if (s8 + 8 < nsteps) {
            const float* pn = pbase + (size_t)(s8 + 8) * 6 * NB;
            #pragma unroll
            for (int u = 0; u < 4; u++)
                #pragma unroll
                for (int k = 0; k < 6; k++)
                    bufA[u][k] = pn[((size_t)u * 6 + k) * NB];
        }
        #pragma unroll
        for (int u = 0; u < 4; u++) {
            const int s = s8 + 4 + u;
            Z_STEP(bufB[u], U)
        }
        if (s8 >= warm) {
            __syncthreads();
            const int tflush0 = town + (s8 - warm);
            for (int f = tid; f < NB * 40; f += 256) {
                int bb = f / 40;
                int u  = f % 40;
                __stcs(&out[OUT_STATES + ((size_t)bb * TT + tflush0) * 5 + u],
                       sbuf[bb * 41 + u]);
            }
            __syncthreads();
        }
    }
    g_llpart[(size_t)b * Z_NCHUNK + chunk] = ll;
}

// ============================================================================
// Kernel 4: ll reduction — block = one batch, 32 lanes, butterfly reduce
// lane reads chunks {lane + 32k, k=0..7} (coalesced), deterministic order
// ============================================================================
__global__ __launch_bounds__(32) void k_ll(float* __restrict__ out)
{
    const int b = blockIdx.x;
    const int lane = threadIdx.x;
    const double* p = &g_llpart[(size_t)b * Z_NCHUNK];
    double s = 0.0;
    #pragma unroll
    for (int k = 0; k < Z_NCHUNK / 32; k++) s += p[lane + k * 32];
    #pragma unroll
    for (int d = 16; d >= 1; d >>= 1)
        s += __shfl_xor_sync(0xFFFFFFFFu, s, d);
    if (lane == 0) out[OUT_LL + b] = (float)s;
}

// ============================================================================
extern "C" void kernel_launch(void* const* d_in, const int* in_sizes, int n_in,
                              void* d_out, int out_size)
{
    const float* y  = (const float*)d_in[0];
    const float* A  = (const float*)d_in[1];
    const float* C  = (const float*)d_in[2];
    const float* Ql = (const float*)d_in[3];
    const float* Rl = (const float*)d_in[4];
    float* out = (float*)d_out;

    cudaFuncSetAttribute(k_projbc, cudaFuncAttributeMaxDynamicSharedMemorySize, P_SMEM);
    cudaFuncSetAttribute(k_z, cudaFuncAttributeMaxDynamicSharedMemorySize, ZB_SMEM);

    k_ricc<<<R_NBLK, 32>>>(A, C, Ql, Rl);
    k_projbc<<<BC_NBLK + P_NBLK, 256, P_SMEM>>>(y, C, Rl, out);
    k_z<<<Z_NCHUNK, 256, ZB_SMEM>>>(A, out);
    k_ll<<<NB, 32>>>(out);
}